// round 1
// baseline (speedup 1.0000x reference)
#include <cuda_runtime.h>
#include <cstdint>

#define TBK      128   // tokens per block
#define NTHREADS 256
#define HID      128
#define NEXP     64
#define LPAD     65    // logits row pad (conflict-free per-token reads)

// ---- device scratch (no allocations allowed) ----
__device__ float              g_Wt[HID * NEXP];     // k-major transposed W
__device__ unsigned long long g_scoreFix[NEXP];     // fixed-point sum of softmax scores
__device__ int                g_cnt[NEXP];          // topk index counts

// ---- f32x2 helpers (Blackwell packed fp32 FMA: 2 FMA/lane/instr) ----
__device__ __forceinline__ unsigned long long pack_dup(float v) {
    unsigned long long r;
    unsigned int b = __float_as_uint(v);
    asm("mov.b64 %0, {%1, %1};" : "=l"(r) : "r"(b));
    return r;
}
__device__ __forceinline__ void ffma2(unsigned long long& d, unsigned long long a,
                                      unsigned long long b) {
    asm("fma.rn.f32x2 %0, %1, %2, %0;" : "+l"(d) : "l"(a), "l"(b));
}
__device__ __forceinline__ void unpack2(unsigned long long v, float& lo, float& hi) {
    unsigned int a, b;
    asm("mov.b64 {%0, %1}, %2;" : "=r"(a), "=r"(b) : "l"(v));
    lo = __uint_as_float(a);
    hi = __uint_as_float(b);
}

// ---- kernel 1: transpose W to k-major, zero accumulators (runs every launch) ----
__global__ void moe_prep(const float* __restrict__ W) {
    int tid = threadIdx.x;
    for (int i = tid; i < HID * NEXP; i += 256) {
        int e = i >> 7;       // expert (row of W)
        int k = i & 127;      // hidden index
        g_Wt[k * NEXP + e] = W[i];
    }
    if (tid < NEXP) {
        g_scoreFix[tid] = 0ull;
        g_cnt[tid]      = 0;
    }
}

// ---- kernel 2: fused gate ----
extern __shared__ float smem[];

__global__ __launch_bounds__(NTHREADS, 2)
void moe_main(const float* __restrict__ x, float* __restrict__ out, int N) {
    float* xs   = smem;                     // [HID][TBK]  64 KB (x transposed)
    float* Ws   = smem + HID * TBK;         // [HID][NEXP] 32 KB (W k-major)
    float* zinv = Ws + HID * NEXP;          // [TBK]
    int*   cntS = (int*)(zinv + TBK);       // [NEXP]
    float* L    = xs;                       // [TBK][LPAD] logits, aliases xs after GEMM

    const int tid = threadIdx.x;
    const long long blk = blockIdx.x;
    const float* xblk = x + blk * (long long)(TBK * HID);

    // --- stage x tile transposed into shared (conflict-free STS) ---
    {
        int t = tid & (TBK - 1);
        int h = tid >> 7;  // 0/1: which half of the hidden dim
        const float4* src = reinterpret_cast<const float4*>(xblk + t * HID + h * 64);
#pragma unroll
        for (int j = 0; j < 16; ++j) {
            float4 v = src[j];
            int k = h * 64 + j * 4;
            xs[(k + 0) * TBK + t] = v.x;
            xs[(k + 1) * TBK + t] = v.y;
            xs[(k + 2) * TBK + t] = v.z;
            xs[(k + 3) * TBK + t] = v.w;
        }
    }
    for (int i = tid; i < HID * NEXP; i += NTHREADS) Ws[i] = g_Wt[i];
    if (tid < NEXP) cntS[tid] = 0;
    __syncthreads();

    // --- register-tiled GEMM: 4 tokens x 8 experts per thread, f32x2 over experts ---
    const int tx = tid & 31;   // token group (4 tokens)
    const int ty = tid >> 5;   // expert group (8 experts)
    unsigned long long acc[4][4];
#pragma unroll
    for (int r = 0; r < 4; ++r)
#pragma unroll
        for (int c = 0; c < 4; ++c) acc[r][c] = 0ull;

    const float* xcol = xs + tx * 4;
    const float* wrow = Ws + ty * 8;

#pragma unroll 8
    for (int k = 0; k < HID; ++k) {
        float4 xv = *reinterpret_cast<const float4*>(xcol + k * TBK);
        ulonglong2 w01 = *reinterpret_cast<const ulonglong2*>(wrow + k * NEXP);
        ulonglong2 w23 = *reinterpret_cast<const ulonglong2*>(wrow + k * NEXP + 4);
        unsigned long long a0 = pack_dup(xv.x);
        unsigned long long a1 = pack_dup(xv.y);
        unsigned long long a2 = pack_dup(xv.z);
        unsigned long long a3 = pack_dup(xv.w);
        ffma2(acc[0][0], a0, w01.x); ffma2(acc[0][1], a0, w01.y);
        ffma2(acc[0][2], a0, w23.x); ffma2(acc[0][3], a0, w23.y);
        ffma2(acc[1][0], a1, w01.x); ffma2(acc[1][1], a1, w01.y);
        ffma2(acc[1][2], a1, w23.x); ffma2(acc[1][3], a1, w23.y);
        ffma2(acc[2][0], a2, w01.x); ffma2(acc[2][1], a2, w01.y);
        ffma2(acc[2][2], a2, w23.x); ffma2(acc[2][3], a2, w23.y);
        ffma2(acc[3][0], a3, w01.x); ffma2(acc[3][1], a3, w01.y);
        ffma2(acc[3][2], a3, w23.x); ffma2(acc[3][3], a3, w23.y);
    }
    __syncthreads();   // everyone done reading xs before we overwrite it with logits

    // --- scatter logits to shared [token][expert] ---
#pragma unroll
    for (int r = 0; r < 4; ++r) {
        int t = tx * 4 + r;
#pragma unroll
        for (int cp = 0; cp < 4; ++cp) {
            float lo, hi;
            unpack2(acc[r][cp], lo, hi);
            int e = ty * 8 + cp * 2;
            L[t * LPAD + e]     = lo;
            L[t * LPAD + e + 1] = hi;
        }
    }
    __syncthreads();

    // --- per-token softmax / top-6 (one thread per token) ---
    if (tid < TBK) {
        const int t = tid;
        float* lr = L + t * LPAD;

        float m = lr[0];
#pragma unroll
        for (int i = 1; i < NEXP; ++i) m = fmaxf(m, lr[i]);

        // 6 argmax passes; strict '>' matches lax.top_k tie-break (lowest index first)
        unsigned long long mask = 0ull;
        int   idxv[6];
        float valv[6];
        for (int j = 0; j < 6; ++j) {
            float best = -1e30f;
            int   bi   = 0;
            for (int i = 0; i < NEXP; ++i) {
                float v = lr[i];
                bool ok = (((mask >> i) & 1ull) == 0ull) && (v > best);
                if (ok) { best = v; bi = i; }
            }
            mask |= (1ull << bi);
            idxv[j] = bi;
            valv[j] = best;
        }

        // full softmax numerators (needed for Pi) — overwrite logits with exps
        float Z = 0.f;
        for (int i = 0; i < NEXP; ++i) {
            float e = __expf(lr[i] - m);
            Z += e;
            lr[i] = e;
        }

        float ev[6];
        float E6 = 0.f;
#pragma unroll
        for (int j = 0; j < 6; ++j) { ev[j] = lr[idxv[j]]; E6 += ev[j]; }

        // ref: w = (e/Z) / (E6/Z + 1e-20)  ==  e / (E6 + 1e-20*Z)
        float invd = 1.f / (E6 + 1e-20f * Z);
        zinv[t] = 1.f / Z;

        size_t gt = (size_t)blk * TBK + t;
        float* oi = out + gt * 6;
        float* ow = out + (size_t)N * 6 + gt * 6;
#pragma unroll
        for (int j = 0; j < 6; ++j) {
            oi[j] = (float)idxv[j];
            ow[j] = ev[j] * invd;
            atomicAdd(&cntS[idxv[j]], 1);   // int: deterministic
        }
    }
    __syncthreads();

    // --- per-expert block partials (fixed order => deterministic), integer global atomics ---
    if (tid < NEXP) {
        float s = 0.f;
        for (int t = 0; t < TBK; ++t) s += L[t * LPAD + tid] * zinv[t];
        unsigned long long fx = (unsigned long long)(s * 1073741824.0f);  // * 2^30
        atomicAdd(&g_scoreFix[tid], fx);
        atomicAdd(&g_cnt[tid], cntS[tid]);
    }
}

// ---- kernel 3: finalize aux loss ----
__global__ void moe_final(float* __restrict__ out, int N) {
    if (threadIdx.x == 0) {
        double aux  = 0.0;
        double invN = 1.0 / (double)N;
        for (int e = 0; e < NEXP; ++e) {
            double Pi = (double)g_scoreFix[e] * (1.0 / 1073741824.0) * invN;
            double fi = (double)g_cnt[e] * 64.0 / ((double)N * 6.0);
            aux += Pi * fi;
        }
        out[(size_t)N * 12] = (float)(aux * 1e-3);
    }
}

extern "C" void kernel_launch(void* const* d_in, const int* in_sizes, int n_in,
                              void* d_out, int out_size) {
    const float* x = (const float*)d_in[0];
    const float* W = (const float*)d_in[1];
    int N = in_sizes[0] / HID;

    int smem_bytes = (HID * TBK + HID * NEXP + TBK) * (int)sizeof(float)
                   + NEXP * (int)sizeof(int);
    cudaFuncSetAttribute(moe_main, cudaFuncAttributeMaxDynamicSharedMemorySize, smem_bytes);

    moe_prep<<<1, 256>>>(W);
    moe_main<<<N / TBK, NTHREADS, smem_bytes>>>(x, (float*)d_out, N);
    moe_final<<<1, 32>>>((float*)d_out, N);
}